// round 10
// baseline (speedup 1.0000x reference)
#include <cuda_runtime.h>
#include <cuda_fp16.h>

#define D      128
#define D4     32
#define DH2    32
#define KHOPS  10
#define BM     32
#define NTHR   256

static const int NMAX = 50000;
static const int EMAX = 625000;
static const int GBMAX = 512;           // max grid blocks we support

// ---------------- scratch (device globals; no allocation allowed) ----------
__device__ __half g_bufA[NMAX * D];     // h ping (fp16 state)
__device__ __half g_bufB[NMAX * D];     // h pong
__device__ int    g_deg[NMAX];
__device__ int    g_rowptr[NMAX + 1];
__device__ int    g_cursor[NMAX];
__device__ float  g_dinv[NMAX];
__device__ int2   g_csr[EMAX];          // {src, bitcast(dinv[src])}
__device__ __half g_Wh[D * D];          // W in fp16, [o][k]
__device__ float  g_coeff[KHOPS + 1];
__device__ int    g_is64;
__device__ int    g_bsum[GBMAX];        // per-block scan partials
__device__ unsigned          g_bar_count;
__device__ volatile unsigned g_bar_gen;

// ---------------- software grid barrier -------------------------------------
__device__ __forceinline__ void gridbar() {
    __syncthreads();
    if (threadIdx.x == 0) {
        __threadfence();                         // release
        unsigned gen = g_bar_gen;
        if (atomicAdd(&g_bar_count, 1u) == gridDim.x - 1) {
            g_bar_count = 0;
            __threadfence();
            g_bar_gen = gen + 1;
        } else {
            while (g_bar_gen == gen) __nanosleep(64);
        }
        __threadfence();                         // acquire
    }
    __syncthreads();
}

// ---------------- block exclusive scan (256 thr); ws = 16 ints shared ------
// returns exclusive prefix; block total left in ws[15]. Caller must
// __syncthreads() before reusing ws.
__device__ __forceinline__ int blk_excl_scan(int v, int* ws) {
    int lane = threadIdx.x & 31, wid = threadIdx.x >> 5;
    int inc = v;
#pragma unroll
    for (int off = 1; off < 32; off <<= 1) {
        int t = __shfl_up_sync(0xffffffffu, inc, off);
        if (lane >= off) inc += t;
    }
    if (lane == 31) ws[wid] = inc;
    __syncthreads();
    if (wid == 0 && lane < 8) {
        int wv = ws[lane];
#pragma unroll
        for (int off = 1; off < 8; off <<= 1) {
            int t = __shfl_up_sync(0xffu, wv, off, 8);
            if (lane >= off) wv += t;
        }
        ws[lane] = wv;
        if (lane == 7) ws[15] = wv;      // total
    }
    __syncthreads();
    return inc - v + (wid ? ws[wid - 1] : 0);
}

__device__ __forceinline__ int load_idx(const void* ei, long long pos) {
    if (g_is64) return (int)((const long long*)ei)[pos];
    return ((const int*)ei)[pos];
}

// ------------- fp16 helpers --------------------------------------------------
__device__ __forceinline__ void fma_h4(uint2 p, float w, float4& a) {
    float2 lo = __half22float2(*(const __half2*)&p.x);
    float2 hi = __half22float2(*(const __half2*)&p.y);
    a.x = fmaf(w, lo.x, a.x); a.y = fmaf(w, lo.y, a.y);
    a.z = fmaf(w, hi.x, a.z); a.w = fmaf(w, hi.y, a.w);
}
__device__ __forceinline__ uint2 pack_h4(float4 r) {
    __half2 lo = __floats2half2_rn(r.x, r.y);
    __half2 hi = __floats2half2_rn(r.z, r.w);
    uint2 p;
    p.x = *(const unsigned int*)&lo;
    p.y = *(const unsigned int*)&hi;
    return p;
}
__device__ __forceinline__ unsigned int smem_u32(const void* p) {
    return (unsigned int)__cvta_generic_to_shared(p);
}

// ================= THE MEGA KERNEL ==========================================
__global__ void __launch_bounds__(NTHR, 2) k_mega(
    const float* __restrict__ x, const void* __restrict__ ei,
    const float* __restrict__ tptr, const float* __restrict__ W,
    const float* __restrict__ bias, float* __restrict__ out, int N, int E)
{
    __shared__ __align__(16) __half sW[D][D + 8];   // 34816 B
    __shared__ __align__(16) __half sA[BM][D + 8];  //  8704 B
    __shared__ int ws[16];

    int tid  = threadIdx.x;
    int bid  = blockIdx.x;
    int lane = tid & 31;
    int warp = tid >> 5;
    int gtid = bid * NTHR + tid;
    int nthr = gridDim.x * NTHR;

    // ---- phase 0: zero deg, W->fp16, coeffs, dtype detect ----
    for (int i = gtid; i < N; i += nthr) g_deg[i] = 0;
    for (int i = gtid; i < D * D; i += nthr) g_Wh[i] = __float2half(W[i]);
    if (gtid == 0) {
        const int* a = (const int*)ei;
        int is64 = 1;
#pragma unroll
        for (int j = 1; j < 32; j += 2)
            if (a[j] != 0) is64 = 0;
        g_is64 = is64;
        float t = *tptr;
        float cc = expf(-t);
        g_coeff[0] = cc;
        for (int k = 1; k <= KHOPS; ++k) { cc = cc * t / (float)k; g_coeff[k] = cc; }
    }
    gridbar();

    // ---- phase 1: degree histogram ----
    for (int e = gtid; e < E; e += nthr) {
        int dst = load_idx(ei, (long long)E + e);
        atomicAdd(&g_deg[dst], 1);
    }
    gridbar();

    // ---- phase 2: per-block partial sums over contiguous chunks ----
    int chunk  = (N + gridDim.x - 1) / gridDim.x;
    int rounds = (chunk + NTHR - 1) / NTHR;
    int base   = bid * chunk;
    {
        int sum = 0;
        for (int r = 0; r < rounds; ++r) {
            int i = base + r * NTHR + tid;
            int v = (i < base + chunk && i < N) ? g_deg[i] : 0;
            int lv = v;
#pragma unroll
            for (int off = 16; off > 0; off >>= 1)
                lv += __shfl_down_sync(0xffffffffu, lv, off);
            if (lane == 0) sum += lv;    // accumulate per warp-leader
        }
        // combine warp leaders
        if (lane == 0) ws[warp] = sum;
        __syncthreads();
        if (warp == 0 && lane < 8) {
            int s = ws[lane];
#pragma unroll
            for (int off = 4; off > 0; off >>= 1)
                s += __shfl_down_sync(0xffu, s, off, 8);
            if (lane == 0) g_bsum[bid] = s;
        }
        __syncthreads();
    }
    gridbar();

    // ---- phase 3: block 0 exclusive-scans the partials ----
    if (bid == 0) {
        int nb = gridDim.x;
        int carry = 0;
        for (int r = 0; r * NTHR < nb; ++r) {
            int i = r * NTHR + tid;
            int v = (i < nb) ? g_bsum[i] : 0;
            int ex = blk_excl_scan(v, ws);
            int tot = ws[15];
            __syncthreads();
            if (i < nb) g_bsum[i] = ex + carry;
            carry += tot;
        }
    }
    gridbar();

    // ---- phase 4: write rowptr / cursor / dinv ----
    {
        int carry = g_bsum[bid];
        for (int r = 0; r < rounds; ++r) {
            int i = base + r * NTHR + tid;
            int inb = (i < base + chunk && i < N);
            int d = inb ? g_deg[i] : 0;
            int ex = blk_excl_scan(d, ws);
            int tot = ws[15];
            __syncthreads();
            if (inb) {
                int excl = ex + carry;
                g_rowptr[i] = excl;
                g_cursor[i] = excl;
                g_dinv[i]   = rsqrtf((float)d + 1.0f);
                if (i == N - 1) g_rowptr[N] = excl + d;
            }
            carry += tot;
        }
    }
    gridbar();

    // ---- phase 5: scatter edges into CSR ----
    for (int e = gtid; e < E; e += nthr) {
        int src = load_idx(ei, e);
        int dst = load_idx(ei, (long long)E + e);
        int pos = atomicAdd(&g_cursor[dst], 1);
        g_csr[pos] = make_int2(src, __float_as_int(g_dinv[src]));
    }
    gridbar();

    // ---- phase 6: HMMA GEMM  y = x W^T ; h0 = fp16(y) ; out = c0*y + b ----
    {
        // W into smem once per block
        const uint4* Wh4 = (const uint4*)g_Wh;
        for (int i = tid; i < D * (D / 8); i += NTHR) {
            int r = i >> 4, c = i & 15;
            *(uint4*)&sW[r][c * 8] = __ldg(&Wh4[r * 16 + c]);
        }
        __syncthreads();

        float c0 = g_coeff[0];
        int rg = warp & 1, cg = warp >> 1;
        int r0 = rg * 16;
        int aRow = r0 + (lane & 15);
        int aCol = (lane >> 4) << 3;
        int bN = (lane & 7) + ((lane >> 4) << 3);
        int bK = ((lane >> 3) & 1) << 3;
        __half2* h0 = (__half2*)g_bufA;

        int ntiles = (N + BM - 1) / BM;
        for (int tile = bid; tile < ntiles; tile += gridDim.x) {
            int rowb = tile * BM;
            int rows = N - rowb; if (rows > BM) rows = BM;

            const float4* x4 = (const float4*)(x + (long long)rowb * D);
            for (int i = tid; i < rows * D4; i += NTHR) {
                int r = i >> 5, c = i & 31;
                float4 v = x4[i];
                *(half2*)&sA[r][c * 4]     = __floats2half2_rn(v.x, v.y);
                *(half2*)&sA[r][c * 4 + 2] = __floats2half2_rn(v.z, v.w);
            }
            __syncthreads();

            float acc[4][4];
#pragma unroll
            for (int j = 0; j < 4; ++j)
#pragma unroll
                for (int q = 0; q < 4; ++q) acc[j][q] = 0.f;

#pragma unroll
            for (int k0 = 0; k0 < D; k0 += 16) {
                unsigned int a0, a1, a2, a3;
                unsigned int aAddr = smem_u32(&sA[aRow][k0 + aCol]);
                asm volatile("ldmatrix.sync.aligned.m8n8.x4.shared.b16 {%0,%1,%2,%3}, [%4];"
                             : "=r"(a0), "=r"(a1), "=r"(a2), "=r"(a3) : "r"(aAddr));
#pragma unroll
                for (int h16 = 0; h16 < 2; ++h16) {
                    int nbase = cg * 32 + h16 * 16;
                    unsigned int b0, b1, b2, b3;
                    unsigned int bAddr = smem_u32(&sW[nbase + bN][k0 + bK]);
                    asm volatile("ldmatrix.sync.aligned.m8n8.x4.shared.b16 {%0,%1,%2,%3}, [%4];"
                                 : "=r"(b0), "=r"(b1), "=r"(b2), "=r"(b3) : "r"(bAddr));
                    int j0 = h16 * 2;
                    asm volatile("mma.sync.aligned.m16n8k16.row.col.f32.f16.f16.f32 "
                                 "{%0,%1,%2,%3},{%4,%5,%6,%7},{%8,%9},{%0,%1,%2,%3};"
                                 : "+f"(acc[j0][0]), "+f"(acc[j0][1]), "+f"(acc[j0][2]), "+f"(acc[j0][3])
                                 : "r"(a0), "r"(a1), "r"(a2), "r"(a3), "r"(b0), "r"(b1));
                    asm volatile("mma.sync.aligned.m16n8k16.row.col.f32.f16.f16.f32 "
                                 "{%0,%1,%2,%3},{%4,%5,%6,%7},{%8,%9},{%0,%1,%2,%3};"
                                 : "+f"(acc[j0+1][0]), "+f"(acc[j0+1][1]), "+f"(acc[j0+1][2]), "+f"(acc[j0+1][3])
                                 : "r"(a0), "r"(a1), "r"(a2), "r"(a3), "r"(b2), "r"(b3));
                }
            }

            int mlo = rowb + r0 + (lane >> 2);
            int mhi = mlo + 8;
#pragma unroll
            for (int j = 0; j < 4; ++j) {
                int col = cg * 32 + j * 8 + ((lane & 3) << 1);
                float2 bb = __ldg((const float2*)(bias + col));
                if (mlo < N) {
                    long long idx = (long long)mlo * D + col;
                    *(float2*)(out + idx) = make_float2(fmaf(c0, acc[j][0], bb.x),
                                                        fmaf(c0, acc[j][1], bb.y));
                    h0[idx >> 1] = __floats2half2_rn(acc[j][0], acc[j][1]);
                }
                if (mhi < N) {
                    long long idx = (long long)mhi * D + col;
                    *(float2*)(out + idx) = make_float2(fmaf(c0, acc[j][2], bb.x),
                                                        fmaf(c0, acc[j][3], bb.y));
                    h0[idx >> 1] = __floats2half2_rn(acc[j][2], acc[j][3]);
                }
            }
            __syncthreads();   // protect sA before next tile
        }
    }
    gridbar();

    // ---- phases 7..16: the 10 diffusion hops ----
    int gw0 = gtid >> 5;
    int nw  = nthr >> 5;
    float4* out4 = (float4*)out;

    for (int k = 1; k <= KHOPS; ++k) {
        int flip    = (k - 1) & 1;
        int do_out  = (k & 1) == 0;
        int write_h = (k < KHOPS);
        const uint2* __restrict__ hin  = flip ? (const uint2*)g_bufB : (const uint2*)g_bufA;
        uint2*       __restrict__ hout = flip ? (uint2*)g_bufA       : (uint2*)g_bufB;
        float cp = g_coeff[k - 1];
        float c  = g_coeff[k];

        for (int gwn = gw0; gwn < N; gwn += nw) {
            int beg = g_rowptr[gwn];
            int end = g_rowptr[gwn + 1];
            uint2 ps = __ldg(&hin[gwn * DH2 + lane]);

            float4 acc  = make_float4(0.f,0.f,0.f,0.f);
            float4 acc2 = make_float4(0.f,0.f,0.f,0.f);

            int e = beg;
            for (; e + 8 <= end; e += 8) {
                int2 c0 = __ldg(&g_csr[e + 0]);
                int2 c1 = __ldg(&g_csr[e + 1]);
                int2 c2 = __ldg(&g_csr[e + 2]);
                int2 c3 = __ldg(&g_csr[e + 3]);
                int2 c4 = __ldg(&g_csr[e + 4]);
                int2 c5 = __ldg(&g_csr[e + 5]);
                int2 c6 = __ldg(&g_csr[e + 6]);
                int2 c7 = __ldg(&g_csr[e + 7]);
                uint2 p0 = __ldg(&hin[c0.x * DH2 + lane]);
                uint2 p1 = __ldg(&hin[c1.x * DH2 + lane]);
                uint2 p2 = __ldg(&hin[c2.x * DH2 + lane]);
                uint2 p3 = __ldg(&hin[c3.x * DH2 + lane]);
                uint2 p4 = __ldg(&hin[c4.x * DH2 + lane]);
                uint2 p5 = __ldg(&hin[c5.x * DH2 + lane]);
                uint2 p6 = __ldg(&hin[c6.x * DH2 + lane]);
                uint2 p7 = __ldg(&hin[c7.x * DH2 + lane]);
                fma_h4(p0, __int_as_float(c0.y), acc);
                fma_h4(p1, __int_as_float(c1.y), acc2);
                fma_h4(p2, __int_as_float(c2.y), acc);
                fma_h4(p3, __int_as_float(c3.y), acc2);
                fma_h4(p4, __int_as_float(c4.y), acc);
                fma_h4(p5, __int_as_float(c5.y), acc2);
                fma_h4(p6, __int_as_float(c6.y), acc);
                fma_h4(p7, __int_as_float(c7.y), acc2);
            }
            for (; e + 4 <= end; e += 4) {
                int2 c0 = __ldg(&g_csr[e + 0]);
                int2 c1 = __ldg(&g_csr[e + 1]);
                int2 c2 = __ldg(&g_csr[e + 2]);
                int2 c3 = __ldg(&g_csr[e + 3]);
                uint2 p0 = __ldg(&hin[c0.x * DH2 + lane]);
                uint2 p1 = __ldg(&hin[c1.x * DH2 + lane]);
                uint2 p2 = __ldg(&hin[c2.x * DH2 + lane]);
                uint2 p3 = __ldg(&hin[c3.x * DH2 + lane]);
                fma_h4(p0, __int_as_float(c0.y), acc);
                fma_h4(p1, __int_as_float(c1.y), acc2);
                fma_h4(p2, __int_as_float(c2.y), acc);
                fma_h4(p3, __int_as_float(c3.y), acc2);
            }
            for (; e < end; ++e) {
                int2 cc = __ldg(&g_csr[e]);
                uint2 p = __ldg(&hin[cc.x * DH2 + lane]);
                fma_h4(p, __int_as_float(cc.y), acc);
            }

            float di  = g_dinv[gwn];
            float di2 = di * di;
            float2 slo = __half22float2(*(const __half2*)&ps.x);
            float2 shi = __half22float2(*(const __half2*)&ps.y);

            float4 r;
            r.x = fmaf(di, acc.x + acc2.x, di2 * slo.x);
            r.y = fmaf(di, acc.y + acc2.y, di2 * slo.y);
            r.z = fmaf(di, acc.z + acc2.z, di2 * shi.x);
            r.w = fmaf(di, acc.w + acc2.w, di2 * shi.y);

            int idx = gwn * DH2 + lane;
            if (write_h) hout[idx] = pack_h4(r);

            if (do_out) {
                float4 o = out4[idx];
                o.x = fmaf(cp, slo.x, o.x);
                o.y = fmaf(cp, slo.y, o.y);
                o.z = fmaf(cp, shi.x, o.z);
                o.w = fmaf(cp, shi.y, o.w);
                o.x = fmaf(c, r.x, o.x);
                o.y = fmaf(c, r.y, o.y);
                o.z = fmaf(c, r.z, o.z);
                o.w = fmaf(c, r.w, o.w);
                out4[idx] = o;
            }
        }
        if (k < KHOPS) gridbar();
    }
}

// ---------------- launch: ONE kernel ----------------------------------------
extern "C" void kernel_launch(void* const* d_in, const int* in_sizes, int n_in,
                              void* d_out, int out_size) {
    const float* x  = (const float*)d_in[0];
    const void*  ei = d_in[1];
    const float* t  = (const float*)d_in[2];
    const float* W  = (const float*)d_in[3];
    const float* b  = (const float*)d_in[4];
    float* out = (float*)d_out;

    int N = in_sizes[0] / D;
    int E = in_sizes[1] / 2;

    // deterministic, co-residency-safe grid size (host-side queries only)
    int dev = 0;
    cudaGetDevice(&dev);
    int nsm = 148, bpm = 1;
    cudaDeviceGetAttribute(&nsm, cudaDevAttrMultiProcessorCount, dev);
    cudaOccupancyMaxActiveBlocksPerMultiprocessor(&bpm, k_mega, NTHR, 0);
    if (bpm < 1) bpm = 1;
    int nblk = nsm * bpm;
    if (nblk > GBMAX) nblk = GBMAX;

    k_mega<<<nblk, NTHR>>>(x, ei, t, W, b, out, N, E);
}

// round 11
// speedup vs baseline: 1.2991x; 1.2991x over previous
#include <cuda_runtime.h>
#include <cuda_fp16.h>

#define D      128
#define D4     32
#define DH2    32
#define KHOPS  10
#define BM     32
#define NTHR   256

static const int NMAX = 50000;
static const int EMAX = 625000;
static const int GBMAX = 1024;          // max grid blocks for persistent kernels

// ---------------- scratch (device globals; no allocation allowed) ----------
__device__ __half g_bufA[NMAX * D];     // h ping (fp16 state)
__device__ __half g_bufB[NMAX * D];     // h pong
__device__ int    g_deg[NMAX];
__device__ int    g_rowptr[NMAX + 1];
__device__ int    g_cursor[NMAX];
__device__ float  g_dinv[NMAX];
__device__ int2   g_csr[EMAX];          // {src, bitcast(dinv[src])}
__device__ __half g_Wh[D * D];          // W in fp16, [o][k]
__device__ float  g_coeff[KHOPS + 1];
__device__ int    g_is64;
__device__ int    g_bsum[GBMAX];        // per-block scan partials
__device__ unsigned          g_bar_count;
__device__ volatile unsigned g_bar_gen;

// ---------------- software grid barrier -------------------------------------
__device__ __forceinline__ void gridbar() {
    __syncthreads();
    if (threadIdx.x == 0) {
        __threadfence();                         // release
        unsigned gen = g_bar_gen;
        if (atomicAdd(&g_bar_count, 1u) == gridDim.x - 1) {
            g_bar_count = 0;
            __threadfence();
            g_bar_gen = gen + 1;
        } else {
            while (g_bar_gen == gen) __nanosleep(64);
        }
        __threadfence();                         // acquire
    }
    __syncthreads();
}

// ---------------- block exclusive scan (256 thr); ws = 16 ints shared ------
__device__ __forceinline__ int blk_excl_scan(int v, int* ws) {
    int lane = threadIdx.x & 31, wid = threadIdx.x >> 5;
    int inc = v;
#pragma unroll
    for (int off = 1; off < 32; off <<= 1) {
        int t = __shfl_up_sync(0xffffffffu, inc, off);
        if (lane >= off) inc += t;
    }
    if (lane == 31) ws[wid] = inc;
    __syncthreads();
    if (wid == 0 && lane < 8) {
        int wv = ws[lane];
#pragma unroll
        for (int off = 1; off < 8; off <<= 1) {
            int t = __shfl_up_sync(0xffu, wv, off, 8);
            if (lane >= off) wv += t;
        }
        ws[lane] = wv;
        if (lane == 7) ws[15] = wv;      // total
    }
    __syncthreads();
    return inc - v + (wid ? ws[wid - 1] : 0);
}

__device__ __forceinline__ int load_idx(const void* ei, long long pos) {
    if (g_is64) return (int)((const long long*)ei)[pos];
    return ((const int*)ei)[pos];
}

// ------------- fp16 helpers --------------------------------------------------
__device__ __forceinline__ void fma_h4(uint2 p, float w, float4& a) {
    float2 lo = __half22float2(*(const __half2*)&p.x);
    float2 hi = __half22float2(*(const __half2*)&p.y);
    a.x = fmaf(w, lo.x, a.x); a.y = fmaf(w, lo.y, a.y);
    a.z = fmaf(w, hi.x, a.z); a.w = fmaf(w, hi.y, a.w);
}
__device__ __forceinline__ uint2 pack_h4(float4 r) {
    __half2 lo = __floats2half2_rn(r.x, r.y);
    __half2 hi = __floats2half2_rn(r.z, r.w);
    uint2 p;
    p.x = *(const unsigned int*)&lo;
    p.y = *(const unsigned int*)&hi;
    return p;
}
__device__ __forceinline__ unsigned int smem_u32(const void* p) {
    return (unsigned int)__cvta_generic_to_shared(p);
}

// ================= LAUNCH 1: persistent preprocessing ======================
// phases: zero/convert -> hist -> blocksum -> scan partials -> write -> scatter
__global__ void __launch_bounds__(NTHR) k_prep(
    const void* __restrict__ ei, const float* __restrict__ tptr,
    const float* __restrict__ W, int N, int E)
{
    __shared__ int ws[16];
    int tid  = threadIdx.x;
    int bid  = blockIdx.x;
    int lane = tid & 31;
    int warp = tid >> 5;
    int gtid = bid * NTHR + tid;
    int nthr = gridDim.x * NTHR;

    // phase 0
    for (int i = gtid; i < N; i += nthr) g_deg[i] = 0;
    for (int i = gtid; i < D * D; i += nthr) g_Wh[i] = __float2half(W[i]);
    if (gtid == 0) {
        const int* a = (const int*)ei;
        int is64 = 1;
#pragma unroll
        for (int j = 1; j < 32; j += 2)
            if (a[j] != 0) is64 = 0;
        g_is64 = is64;
        float t = *tptr;
        float cc = expf(-t);
        g_coeff[0] = cc;
        for (int k = 1; k <= KHOPS; ++k) { cc = cc * t / (float)k; g_coeff[k] = cc; }
    }
    gridbar();

    // phase 1: histogram
    for (int e = gtid; e < E; e += nthr) {
        int dst = load_idx(ei, (long long)E + e);
        atomicAdd(&g_deg[dst], 1);
    }
    gridbar();

    // phase 2: per-block partials over contiguous chunks
    int chunk  = (N + gridDim.x - 1) / gridDim.x;
    int rounds = (chunk + NTHR - 1) / NTHR;
    int base   = bid * chunk;
    {
        int sum = 0;
        for (int r = 0; r < rounds; ++r) {
            int i = base + r * NTHR + tid;
            int v = (i < base + chunk && i < N) ? g_deg[i] : 0;
#pragma unroll
            for (int off = 16; off > 0; off >>= 1)
                v += __shfl_down_sync(0xffffffffu, v, off);
            if (lane == 0) sum += v;
        }
        if (lane == 0) ws[warp] = sum;
        __syncthreads();
        if (warp == 0 && lane < 8) {
            int s = ws[lane];
#pragma unroll
            for (int off = 4; off > 0; off >>= 1)
                s += __shfl_down_sync(0xffu, s, off, 8);
            if (lane == 0) g_bsum[bid] = s;
        }
        __syncthreads();
    }
    gridbar();

    // phase 3: block 0 scans partials
    if (bid == 0) {
        int nb = gridDim.x;
        int carry = 0;
        for (int r = 0; r * NTHR < nb; ++r) {
            int i = r * NTHR + tid;
            int v = (i < nb) ? g_bsum[i] : 0;
            int ex = blk_excl_scan(v, ws);
            int tot = ws[15];
            __syncthreads();
            if (i < nb) g_bsum[i] = ex + carry;
            carry += tot;
        }
    }
    gridbar();

    // phase 4: write rowptr / cursor / dinv
    {
        int carry = g_bsum[bid];
        for (int r = 0; r < rounds; ++r) {
            int i = base + r * NTHR + tid;
            int inb = (i < base + chunk && i < N);
            int d = inb ? g_deg[i] : 0;
            int ex = blk_excl_scan(d, ws);
            int tot = ws[15];
            __syncthreads();
            if (inb) {
                int excl = ex + carry;
                g_rowptr[i] = excl;
                g_cursor[i] = excl;
                g_dinv[i]   = rsqrtf((float)d + 1.0f);
                if (i == N - 1) g_rowptr[N] = excl + d;
            }
            carry += tot;
        }
    }
    gridbar();

    // phase 5: scatter
    for (int e = gtid; e < E; e += nthr) {
        int src = load_idx(ei, e);
        int dst = load_idx(ei, (long long)E + e);
        int pos = atomicAdd(&g_cursor[dst], 1);
        g_csr[pos] = make_int2(src, __float_as_int(g_dinv[src]));
    }
}

// ================= LAUNCH 2: HMMA GEMM (R8, known good) ====================
__global__ void __launch_bounds__(256) k_gemm_mma(
    const float* __restrict__ x, const float* __restrict__ b,
    float* __restrict__ out, int n)
{
    __shared__ __align__(16) __half sA[BM][D + 8];
    __shared__ __align__(16) __half sW[D][D + 8];

    int tid  = threadIdx.x;
    int warp = tid >> 5;
    int lane = tid & 31;
    int rowb = blockIdx.x * BM;
    int rows = n - rowb; if (rows > BM) rows = BM;

    const uint4* Wh4 = (const uint4*)g_Wh;
#pragma unroll
    for (int i = tid; i < D * (D / 8); i += 256) {
        int r = i >> 4, c = i & 15;
        *(uint4*)&sW[r][c * 8] = __ldg(&Wh4[r * 16 + c]);
    }
    const float4* x4 = (const float4*)(x + (long long)rowb * D);
    for (int i = tid; i < rows * D4; i += 256) {
        int r = i >> 5, c = i & 31;
        float4 v = x4[i];
        *(half2*)&sA[r][c * 4]     = __floats2half2_rn(v.x, v.y);
        *(half2*)&sA[r][c * 4 + 2] = __floats2half2_rn(v.z, v.w);
    }
    __syncthreads();

    int rg = warp & 1, cg = warp >> 1;
    int r0 = rg * 16;

    float acc[4][4];
#pragma unroll
    for (int j = 0; j < 4; ++j)
#pragma unroll
        for (int q = 0; q < 4; ++q) acc[j][q] = 0.f;

    int aRow = r0 + (lane & 15);
    int aCol = (lane >> 4) << 3;
    int bN = (lane & 7) + ((lane >> 4) << 3);
    int bK = ((lane >> 3) & 1) << 3;

#pragma unroll
    for (int k0 = 0; k0 < D; k0 += 16) {
        unsigned int a0, a1, a2, a3;
        unsigned int aAddr = smem_u32(&sA[aRow][k0 + aCol]);
        asm volatile("ldmatrix.sync.aligned.m8n8.x4.shared.b16 {%0,%1,%2,%3}, [%4];"
                     : "=r"(a0), "=r"(a1), "=r"(a2), "=r"(a3) : "r"(aAddr));
#pragma unroll
        for (int h16 = 0; h16 < 2; ++h16) {
            int nbase = cg * 32 + h16 * 16;
            unsigned int b0, b1, b2, b3;
            unsigned int bAddr = smem_u32(&sW[nbase + bN][k0 + bK]);
            asm volatile("ldmatrix.sync.aligned.m8n8.x4.shared.b16 {%0,%1,%2,%3}, [%4];"
                         : "=r"(b0), "=r"(b1), "=r"(b2), "=r"(b3) : "r"(bAddr));
            int j0 = h16 * 2;
            asm volatile("mma.sync.aligned.m16n8k16.row.col.f32.f16.f16.f32 "
                         "{%0,%1,%2,%3},{%4,%5,%6,%7},{%8,%9},{%0,%1,%2,%3};"
                         : "+f"(acc[j0][0]), "+f"(acc[j0][1]), "+f"(acc[j0][2]), "+f"(acc[j0][3])
                         : "r"(a0), "r"(a1), "r"(a2), "r"(a3), "r"(b0), "r"(b1));
            asm volatile("mma.sync.aligned.m16n8k16.row.col.f32.f16.f16.f32 "
                         "{%0,%1,%2,%3},{%4,%5,%6,%7},{%8,%9},{%0,%1,%2,%3};"
                         : "+f"(acc[j0+1][0]), "+f"(acc[j0+1][1]), "+f"(acc[j0+1][2]), "+f"(acc[j0+1][3])
                         : "r"(a0), "r"(a1), "r"(a2), "r"(a3), "r"(b2), "r"(b3));
        }
    }

    float c0 = g_coeff[0];
    int mlo = rowb + r0 + (lane >> 2);
    int mhi = mlo + 8;
    __half2* h0 = (__half2*)g_bufA;

#pragma unroll
    for (int j = 0; j < 4; ++j) {
        int col = cg * 32 + j * 8 + ((lane & 3) << 1);
        float2 bb = __ldg((const float2*)(b + col));
        if (mlo < n) {
            long long idx = (long long)mlo * D + col;
            *(float2*)(out + idx) = make_float2(fmaf(c0, acc[j][0], bb.x),
                                                fmaf(c0, acc[j][1], bb.y));
            h0[idx >> 1] = __floats2half2_rn(acc[j][0], acc[j][1]);
        }
        if (mhi < n) {
            long long idx = (long long)mhi * D + col;
            *(float2*)(out + idx) = make_float2(fmaf(c0, acc[j][2], bb.x),
                                                fmaf(c0, acc[j][3], bb.y));
            h0[idx >> 1] = __floats2half2_rn(acc[j][2], acc[j][3]);
        }
    }
}

// ================= LAUNCH 3: persistent 10-hop kernel =======================
// NOTE: hin is re-written each hop by other SMs -> all hin reads use __ldcg
// (L2 coherence point). CSR/rowptr/dinv were written in a PRIOR launch (L1
// flushed at launch boundary) so __ldg is safe for them.
__global__ void __launch_bounds__(NTHR) k_hops(int N, float4* __restrict__ out4)
{
    int lane = threadIdx.x & 31;
    int gw0  = (blockIdx.x * NTHR + threadIdx.x) >> 5;
    int nw   = (gridDim.x * NTHR) >> 5;

    for (int k = 1; k <= KHOPS; ++k) {
        int flip    = (k - 1) & 1;
        int do_out  = (k & 1) == 0;
        int write_h = (k < KHOPS);
        const uint2* __restrict__ hin  = flip ? (const uint2*)g_bufB : (const uint2*)g_bufA;
        uint2*       __restrict__ hout = flip ? (uint2*)g_bufA       : (uint2*)g_bufB;
        float cp = g_coeff[k - 1];
        float c  = g_coeff[k];

        for (int gwn = gw0; gwn < N; gwn += nw) {
            int beg = __ldg(&g_rowptr[gwn]);
            int end = __ldg(&g_rowptr[gwn + 1]);
            uint2 ps = __ldcg(&hin[gwn * DH2 + lane]);

            float4 acc  = make_float4(0.f,0.f,0.f,0.f);
            float4 acc2 = make_float4(0.f,0.f,0.f,0.f);

            int e = beg;
            for (; e + 8 <= end; e += 8) {
                int2 c0 = __ldg(&g_csr[e + 0]);
                int2 c1 = __ldg(&g_csr[e + 1]);
                int2 c2 = __ldg(&g_csr[e + 2]);
                int2 c3 = __ldg(&g_csr[e + 3]);
                int2 c4 = __ldg(&g_csr[e + 4]);
                int2 c5 = __ldg(&g_csr[e + 5]);
                int2 c6 = __ldg(&g_csr[e + 6]);
                int2 c7 = __ldg(&g_csr[e + 7]);
                uint2 p0 = __ldcg(&hin[c0.x * DH2 + lane]);
                uint2 p1 = __ldcg(&hin[c1.x * DH2 + lane]);
                uint2 p2 = __ldcg(&hin[c2.x * DH2 + lane]);
                uint2 p3 = __ldcg(&hin[c3.x * DH2 + lane]);
                uint2 p4 = __ldcg(&hin[c4.x * DH2 + lane]);
                uint2 p5 = __ldcg(&hin[c5.x * DH2 + lane]);
                uint2 p6 = __ldcg(&hin[c6.x * DH2 + lane]);
                uint2 p7 = __ldcg(&hin[c7.x * DH2 + lane]);
                fma_h4(p0, __int_as_float(c0.y), acc);
                fma_h4(p1, __int_as_float(c1.y), acc2);
                fma_h4(p2, __int_as_float(c2.y), acc);
                fma_h4(p3, __int_as_float(c3.y), acc2);
                fma_h4(p4, __int_as_float(c4.y), acc);
                fma_h4(p5, __int_as_float(c5.y), acc2);
                fma_h4(p6, __int_as_float(c6.y), acc);
                fma_h4(p7, __int_as_float(c7.y), acc2);
            }
            for (; e + 4 <= end; e += 4) {
                int2 c0 = __ldg(&g_csr[e + 0]);
                int2 c1 = __ldg(&g_csr[e + 1]);
                int2 c2 = __ldg(&g_csr[e + 2]);
                int2 c3 = __ldg(&g_csr[e + 3]);
                uint2 p0 = __ldcg(&hin[c0.x * DH2 + lane]);
                uint2 p1 = __ldcg(&hin[c1.x * DH2 + lane]);
                uint2 p2 = __ldcg(&hin[c2.x * DH2 + lane]);
                uint2 p3 = __ldcg(&hin[c3.x * DH2 + lane]);
                fma_h4(p0, __int_as_float(c0.y), acc);
                fma_h4(p1, __int_as_float(c1.y), acc2);
                fma_h4(p2, __int_as_float(c2.y), acc);
                fma_h4(p3, __int_as_float(c3.y), acc2);
            }
            for (; e < end; ++e) {
                int2 cc = __ldg(&g_csr[e]);
                uint2 p = __ldcg(&hin[cc.x * DH2 + lane]);
                fma_h4(p, __int_as_float(cc.y), acc);
            }

            float di  = __ldg(&g_dinv[gwn]);
            float di2 = di * di;
            float2 slo = __half22float2(*(const __half2*)&ps.x);
            float2 shi = __half22float2(*(const __half2*)&ps.y);

            float4 r;
            r.x = fmaf(di, acc.x + acc2.x, di2 * slo.x);
            r.y = fmaf(di, acc.y + acc2.y, di2 * slo.y);
            r.z = fmaf(di, acc.z + acc2.z, di2 * shi.x);
            r.w = fmaf(di, acc.w + acc2.w, di2 * shi.y);

            int idx = gwn * DH2 + lane;
            if (write_h) hout[idx] = pack_h4(r);

            if (do_out) {
                float4 o = out4[idx];
                o.x = fmaf(cp, slo.x, o.x);
                o.y = fmaf(cp, slo.y, o.y);
                o.z = fmaf(cp, shi.x, o.z);
                o.w = fmaf(cp, shi.y, o.w);
                o.x = fmaf(c, r.x, o.x);
                o.y = fmaf(c, r.y, o.y);
                o.z = fmaf(c, r.z, o.z);
                o.w = fmaf(c, r.w, o.w);
                out4[idx] = o;
            }
        }
        if (k < KHOPS) gridbar();
    }
}

// ---------------- launch: THREE kernels --------------------------------------
extern "C" void kernel_launch(void* const* d_in, const int* in_sizes, int n_in,
                              void* d_out, int out_size) {
    const float* x  = (const float*)d_in[0];
    const void*  ei = d_in[1];
    const float* t  = (const float*)d_in[2];
    const float* W  = (const float*)d_in[3];
    const float* b  = (const float*)d_in[4];
    float* out = (float*)d_out;

    int N = in_sizes[0] / D;
    int E = in_sizes[1] / 2;

    int dev = 0;
    cudaGetDevice(&dev);
    int nsm = 148;
    cudaDeviceGetAttribute(&nsm, cudaDevAttrMultiProcessorCount, dev);

    int bpm_prep = 1, bpm_hops = 1;
    cudaOccupancyMaxActiveBlocksPerMultiprocessor(&bpm_prep, k_prep, NTHR, 0);
    cudaOccupancyMaxActiveBlocksPerMultiprocessor(&bpm_hops, k_hops, NTHR, 0);
    if (bpm_prep < 1) bpm_prep = 1;
    if (bpm_hops < 1) bpm_hops = 1;
    int nb_prep = nsm * bpm_prep; if (nb_prep > GBMAX) nb_prep = GBMAX;
    int nb_hops = nsm * bpm_hops; if (nb_hops > GBMAX) nb_hops = GBMAX;

    k_prep<<<nb_prep, NTHR>>>(ei, t, W, N, E);
    k_gemm_mma<<<(N + BM - 1) / BM, 256>>>(x, b, out, N);
    k_hops<<<nb_hops, NTHR>>>(N, (float4*)out);
}

// round 12
// speedup vs baseline: 1.4595x; 1.1235x over previous
#include <cuda_runtime.h>
#include <cuda_fp16.h>

#define D      128
#define D4     32
#define DH2    32
#define KHOPS  10
#define BM     32
#define NTHR   256

static const int NMAX = 50000;
static const int EMAX = 625000;
static const int GBMAX = 512;           // cap for prep grid

// ---------------- scratch (device globals; no allocation allowed) ----------
__device__ __half g_bufA[NMAX * D];     // h ping (fp16 state)
__device__ __half g_bufB[NMAX * D];     // h pong
__device__ int    g_deg[NMAX];
__device__ int    g_rowptr[NMAX + 1];
__device__ int    g_cursor[NMAX];
__device__ float  g_dinv[NMAX];
__device__ int2   g_csr[EMAX];          // {src, bitcast(dinv[src])}
__device__ __half g_Wh[D * D];          // W in fp16, [o][k]
__device__ float  g_coeff[KHOPS + 1];
__device__ int    g_is64;
__device__ int    g_bsum[GBMAX];        // per-block scan partials
__device__ unsigned          g_bar_count;
__device__ volatile unsigned g_bar_gen;

// ---------------- software grid barrier -------------------------------------
__device__ __forceinline__ void gridbar() {
    __syncthreads();
    if (threadIdx.x == 0) {
        __threadfence();                         // release
        unsigned gen = g_bar_gen;
        if (atomicAdd(&g_bar_count, 1u) == gridDim.x - 1) {
            g_bar_count = 0;
            __threadfence();
            g_bar_gen = gen + 1;
        } else {
            while (g_bar_gen == gen) __nanosleep(64);
        }
        __threadfence();                         // acquire
    }
    __syncthreads();
}

// ---------------- block exclusive scan (256 thr); ws = 16 ints shared ------
__device__ __forceinline__ int blk_excl_scan(int v, int* ws) {
    int lane = threadIdx.x & 31, wid = threadIdx.x >> 5;
    int inc = v;
#pragma unroll
    for (int off = 1; off < 32; off <<= 1) {
        int t = __shfl_up_sync(0xffffffffu, inc, off);
        if (lane >= off) inc += t;
    }
    if (lane == 31) ws[wid] = inc;
    __syncthreads();
    if (wid == 0 && lane < 8) {
        int wv = ws[lane];
#pragma unroll
        for (int off = 1; off < 8; off <<= 1) {
            int t = __shfl_up_sync(0xffu, wv, off, 8);
            if (lane >= off) wv += t;
        }
        ws[lane] = wv;
        if (lane == 7) ws[15] = wv;      // total
    }
    __syncthreads();
    return inc - v + (wid ? ws[wid - 1] : 0);
}

__device__ __forceinline__ int load_idx(const void* ei, long long pos) {
    if (g_is64) return (int)((const long long*)ei)[pos];
    return ((const int*)ei)[pos];
}

// ------------- fp16 helpers --------------------------------------------------
__device__ __forceinline__ void fma_h4(uint2 p, float w, float4& a) {
    float2 lo = __half22float2(*(const __half2*)&p.x);
    float2 hi = __half22float2(*(const __half2*)&p.y);
    a.x = fmaf(w, lo.x, a.x); a.y = fmaf(w, lo.y, a.y);
    a.z = fmaf(w, hi.x, a.z); a.w = fmaf(w, hi.y, a.w);
}
__device__ __forceinline__ uint2 pack_h4(float4 r) {
    __half2 lo = __floats2half2_rn(r.x, r.y);
    __half2 hi = __floats2half2_rn(r.z, r.w);
    uint2 p;
    p.x = *(const unsigned int*)&lo;
    p.y = *(const unsigned int*)&hi;
    return p;
}
__device__ __forceinline__ unsigned int smem_u32(const void* p) {
    return (unsigned int)__cvta_generic_to_shared(p);
}

// ================= LAUNCH 1: persistent preprocessing (small grid) ==========
__global__ void __launch_bounds__(NTHR) k_prep(
    const void* __restrict__ ei, const float* __restrict__ tptr,
    const float* __restrict__ W, int N, int E)
{
    __shared__ int ws[16];
    int tid  = threadIdx.x;
    int bid  = blockIdx.x;
    int lane = tid & 31;
    int warp = tid >> 5;
    int gtid = bid * NTHR + tid;
    int nthr = gridDim.x * NTHR;

    // phase 0: zero deg, W->fp16, coeffs, dtype detect
    for (int i = gtid; i < N; i += nthr) g_deg[i] = 0;
    for (int i = gtid; i < D * D; i += nthr) g_Wh[i] = __float2half(W[i]);
    if (gtid == 0) {
        const int* a = (const int*)ei;
        int is64 = 1;
#pragma unroll
        for (int j = 1; j < 32; j += 2)
            if (a[j] != 0) is64 = 0;
        g_is64 = is64;
        float t = *tptr;
        float cc = expf(-t);
        g_coeff[0] = cc;
        for (int k = 1; k <= KHOPS; ++k) { cc = cc * t / (float)k; g_coeff[k] = cc; }
    }
    gridbar();

    // phase 1: histogram
    for (int e = gtid; e < E; e += nthr) {
        int dst = load_idx(ei, (long long)E + e);
        atomicAdd(&g_deg[dst], 1);
    }
    gridbar();

    // phase 2: per-block partial sums over contiguous chunks
    int chunk  = (N + gridDim.x - 1) / gridDim.x;
    int rounds = (chunk + NTHR - 1) / NTHR;
    int base   = bid * chunk;
    {
        int sum = 0;
        for (int r = 0; r < rounds; ++r) {
            int i = base + r * NTHR + tid;
            int v = (i < base + chunk && i < N) ? g_deg[i] : 0;
#pragma unroll
            for (int off = 16; off > 0; off >>= 1)
                v += __shfl_down_sync(0xffffffffu, v, off);
            if (lane == 0) sum += v;
        }
        if (lane == 0) ws[warp] = sum;
        __syncthreads();
        if (warp == 0 && lane < 8) {
            int s = ws[lane];
#pragma unroll
            for (int off = 4; off > 0; off >>= 1)
                s += __shfl_down_sync(0xffu, s, off, 8);
            if (lane == 0) g_bsum[bid] = s;
        }
        __syncthreads();
    }
    gridbar();

    // phase 3: block 0 scans partials
    if (bid == 0) {
        int nb = gridDim.x;
        int carry = 0;
        for (int r = 0; r * NTHR < nb; ++r) {
            int i = r * NTHR + tid;
            int v = (i < nb) ? g_bsum[i] : 0;
            int ex = blk_excl_scan(v, ws);
            int tot = ws[15];
            __syncthreads();
            if (i < nb) g_bsum[i] = ex + carry;
            carry += tot;
        }
    }
    gridbar();

    // phase 4: write rowptr / cursor / dinv
    {
        int carry = g_bsum[bid];
        for (int r = 0; r < rounds; ++r) {
            int i = base + r * NTHR + tid;
            int inb = (i < base + chunk && i < N);
            int d = inb ? g_deg[i] : 0;
            int ex = blk_excl_scan(d, ws);
            int tot = ws[15];
            __syncthreads();
            if (inb) {
                int excl = ex + carry;
                g_rowptr[i] = excl;
                g_cursor[i] = excl;
                g_dinv[i]   = rsqrtf((float)d + 1.0f);
                if (i == N - 1) g_rowptr[N] = excl + d;
            }
            carry += tot;
        }
    }
    gridbar();

    // phase 5: scatter
    for (int e = gtid; e < E; e += nthr) {
        int src = load_idx(ei, e);
        int dst = load_idx(ei, (long long)E + e);
        int pos = atomicAdd(&g_cursor[dst], 1);
        g_csr[pos] = make_int2(src, __float_as_int(g_dinv[src]));
    }
}

// ================= LAUNCH 2: HMMA GEMM (R8, known good) ====================
__global__ void __launch_bounds__(256) k_gemm_mma(
    const float* __restrict__ x, const float* __restrict__ b,
    float* __restrict__ out, int n)
{
    __shared__ __align__(16) __half sA[BM][D + 8];
    __shared__ __align__(16) __half sW[D][D + 8];

    int tid  = threadIdx.x;
    int warp = tid >> 5;
    int lane = tid & 31;
    int rowb = blockIdx.x * BM;
    int rows = n - rowb; if (rows > BM) rows = BM;

    const uint4* Wh4 = (const uint4*)g_Wh;
#pragma unroll
    for (int i = tid; i < D * (D / 8); i += 256) {
        int r = i >> 4, c = i & 15;
        *(uint4*)&sW[r][c * 8] = __ldg(&Wh4[r * 16 + c]);
    }
    const float4* x4 = (const float4*)(x + (long long)rowb * D);
    for (int i = tid; i < rows * D4; i += 256) {
        int r = i >> 5, c = i & 31;
        float4 v = x4[i];
        *(half2*)&sA[r][c * 4]     = __floats2half2_rn(v.x, v.y);
        *(half2*)&sA[r][c * 4 + 2] = __floats2half2_rn(v.z, v.w);
    }
    __syncthreads();

    int rg = warp & 1, cg = warp >> 1;
    int r0 = rg * 16;

    float acc[4][4];
#pragma unroll
    for (int j = 0; j < 4; ++j)
#pragma unroll
        for (int q = 0; q < 4; ++q) acc[j][q] = 0.f;

    int aRow = r0 + (lane & 15);
    int aCol = (lane >> 4) << 3;
    int bN = (lane & 7) + ((lane >> 4) << 3);
    int bK = ((lane >> 3) & 1) << 3;

#pragma unroll
    for (int k0 = 0; k0 < D; k0 += 16) {
        unsigned int a0, a1, a2, a3;
        unsigned int aAddr = smem_u32(&sA[aRow][k0 + aCol]);
        asm volatile("ldmatrix.sync.aligned.m8n8.x4.shared.b16 {%0,%1,%2,%3}, [%4];"
                     : "=r"(a0), "=r"(a1), "=r"(a2), "=r"(a3) : "r"(aAddr));
#pragma unroll
        for (int h16 = 0; h16 < 2; ++h16) {
            int nbase = cg * 32 + h16 * 16;
            unsigned int b0, b1, b2, b3;
            unsigned int bAddr = smem_u32(&sW[nbase + bN][k0 + bK]);
            asm volatile("ldmatrix.sync.aligned.m8n8.x4.shared.b16 {%0,%1,%2,%3}, [%4];"
                         : "=r"(b0), "=r"(b1), "=r"(b2), "=r"(b3) : "r"(bAddr));
            int j0 = h16 * 2;
            asm volatile("mma.sync.aligned.m16n8k16.row.col.f32.f16.f16.f32 "
                         "{%0,%1,%2,%3},{%4,%5,%6,%7},{%8,%9},{%0,%1,%2,%3};"
                         : "+f"(acc[j0][0]), "+f"(acc[j0][1]), "+f"(acc[j0][2]), "+f"(acc[j0][3])
                         : "r"(a0), "r"(a1), "r"(a2), "r"(a3), "r"(b0), "r"(b1));
            asm volatile("mma.sync.aligned.m16n8k16.row.col.f32.f16.f16.f32 "
                         "{%0,%1,%2,%3},{%4,%5,%6,%7},{%8,%9},{%0,%1,%2,%3};"
                         : "+f"(acc[j0+1][0]), "+f"(acc[j0+1][1]), "+f"(acc[j0+1][2]), "+f"(acc[j0+1][3])
                         : "r"(a0), "r"(a1), "r"(a2), "r"(a3), "r"(b2), "r"(b3));
        }
    }

    float c0 = g_coeff[0];
    int mlo = rowb + r0 + (lane >> 2);
    int mhi = mlo + 8;
    __half2* h0 = (__half2*)g_bufA;

#pragma unroll
    for (int j = 0; j < 4; ++j) {
        int col = cg * 32 + j * 8 + ((lane & 3) << 1);
        float2 bb = __ldg((const float2*)(b + col));
        if (mlo < n) {
            long long idx = (long long)mlo * D + col;
            *(float2*)(out + idx) = make_float2(fmaf(c0, acc[j][0], bb.x),
                                                fmaf(c0, acc[j][1], bb.y));
            h0[idx >> 1] = __floats2half2_rn(acc[j][0], acc[j][1]);
        }
        if (mhi < n) {
            long long idx = (long long)mhi * D + col;
            *(float2*)(out + idx) = make_float2(fmaf(c0, acc[j][2], bb.x),
                                                fmaf(c0, acc[j][3], bb.y));
            h0[idx >> 1] = __floats2half2_rn(acc[j][2], acc[j][3]);
        }
    }
}

// ================= LAUNCH 3..12: one diffusion hop (R8, known good) =========
__global__ void __launch_bounds__(256) k_hop(
    int flip, int k, int n, float4* __restrict__ out, int do_out, int write_h)
{
    int gw = (blockIdx.x * blockDim.x + threadIdx.x) >> 5;
    if (gw >= n) return;
    int lane = threadIdx.x & 31;

    const uint2* __restrict__ hin  = flip ? (const uint2*)g_bufB : (const uint2*)g_bufA;
    uint2*       __restrict__ hout = flip ? (uint2*)g_bufA       : (uint2*)g_bufB;

    int beg = g_rowptr[gw];
    int end = g_rowptr[gw + 1];

    uint2 ps = __ldg(&hin[gw * DH2 + lane]);

    float4 acc  = make_float4(0.f,0.f,0.f,0.f);
    float4 acc2 = make_float4(0.f,0.f,0.f,0.f);

    int e = beg;
    for (; e + 8 <= end; e += 8) {
        int2 c0 = __ldg(&g_csr[e + 0]);
        int2 c1 = __ldg(&g_csr[e + 1]);
        int2 c2 = __ldg(&g_csr[e + 2]);
        int2 c3 = __ldg(&g_csr[e + 3]);
        int2 c4 = __ldg(&g_csr[e + 4]);
        int2 c5 = __ldg(&g_csr[e + 5]);
        int2 c6 = __ldg(&g_csr[e + 6]);
        int2 c7 = __ldg(&g_csr[e + 7]);
        uint2 p0 = __ldg(&hin[c0.x * DH2 + lane]);
        uint2 p1 = __ldg(&hin[c1.x * DH2 + lane]);
        uint2 p2 = __ldg(&hin[c2.x * DH2 + lane]);
        uint2 p3 = __ldg(&hin[c3.x * DH2 + lane]);
        uint2 p4 = __ldg(&hin[c4.x * DH2 + lane]);
        uint2 p5 = __ldg(&hin[c5.x * DH2 + lane]);
        uint2 p6 = __ldg(&hin[c6.x * DH2 + lane]);
        uint2 p7 = __ldg(&hin[c7.x * DH2 + lane]);
        fma_h4(p0, __int_as_float(c0.y), acc);
        fma_h4(p1, __int_as_float(c1.y), acc2);
        fma_h4(p2, __int_as_float(c2.y), acc);
        fma_h4(p3, __int_as_float(c3.y), acc2);
        fma_h4(p4, __int_as_float(c4.y), acc);
        fma_h4(p5, __int_as_float(c5.y), acc2);
        fma_h4(p6, __int_as_float(c6.y), acc);
        fma_h4(p7, __int_as_float(c7.y), acc2);
    }
    for (; e + 4 <= end; e += 4) {
        int2 c0 = __ldg(&g_csr[e + 0]);
        int2 c1 = __ldg(&g_csr[e + 1]);
        int2 c2 = __ldg(&g_csr[e + 2]);
        int2 c3 = __ldg(&g_csr[e + 3]);
        uint2 p0 = __ldg(&hin[c0.x * DH2 + lane]);
        uint2 p1 = __ldg(&hin[c1.x * DH2 + lane]);
        uint2 p2 = __ldg(&hin[c2.x * DH2 + lane]);
        uint2 p3 = __ldg(&hin[c3.x * DH2 + lane]);
        fma_h4(p0, __int_as_float(c0.y), acc);
        fma_h4(p1, __int_as_float(c1.y), acc2);
        fma_h4(p2, __int_as_float(c2.y), acc);
        fma_h4(p3, __int_as_float(c3.y), acc2);
    }
    for (; e < end; ++e) {
        int2 c = __ldg(&g_csr[e]);
        uint2 p = __ldg(&hin[c.x * DH2 + lane]);
        fma_h4(p, __int_as_float(c.y), acc);
    }

    float di  = g_dinv[gw];
    float di2 = di * di;
    float2 slo = __half22float2(*(const __half2*)&ps.x);
    float2 shi = __half22float2(*(const __half2*)&ps.y);

    float4 r;
    r.x = fmaf(di, acc.x + acc2.x, di2 * slo.x);
    r.y = fmaf(di, acc.y + acc2.y, di2 * slo.y);
    r.z = fmaf(di, acc.z + acc2.z, di2 * shi.x);
    r.w = fmaf(di, acc.w + acc2.w, di2 * shi.y);

    int idx = gw * DH2 + lane;
    if (write_h) hout[idx] = pack_h4(r);

    if (do_out) {
        float cp = g_coeff[k - 1];
        float c  = g_coeff[k];
        float4 o = out[idx];
        o.x = fmaf(cp, slo.x, o.x);
        o.y = fmaf(cp, slo.y, o.y);
        o.z = fmaf(cp, shi.x, o.z);
        o.w = fmaf(cp, shi.y, o.w);
        o.x = fmaf(c, r.x, o.x);
        o.y = fmaf(c, r.y, o.y);
        o.z = fmaf(c, r.z, o.z);
        o.w = fmaf(c, r.w, o.w);
        out[idx] = o;
    }
}

// ---------------- launch ------------------------------------------------------
extern "C" void kernel_launch(void* const* d_in, const int* in_sizes, int n_in,
                              void* d_out, int out_size) {
    const float* x  = (const float*)d_in[0];
    const void*  ei = d_in[1];
    const float* t  = (const float*)d_in[2];
    const float* W  = (const float*)d_in[3];
    const float* b  = (const float*)d_in[4];
    float* out = (float*)d_out;

    int N = in_sizes[0] / D;
    int E = in_sizes[1] / 2;

    int dev = 0;
    cudaGetDevice(&dev);
    int nsm = 148;
    cudaDeviceGetAttribute(&nsm, cudaDevAttrMultiProcessorCount, dev);

    // prep grid: 2 blocks/SM — enough parallelism, cheap barriers
    int nb_prep = nsm * 2;
    if (nb_prep > GBMAX) nb_prep = GBMAX;

    k_prep<<<nb_prep, NTHR>>>(ei, t, W, N, E);
    k_gemm_mma<<<(N + BM - 1) / BM, 256>>>(x, b, out, N);

    int hop_blocks = (N + 7) / 8;   // 8 warps per block, warp per node
    for (int k = 1; k <= KHOPS; ++k) {
        int flip    = (k - 1) & 1;
        int do_out  = (k & 1) == 0;
        int write_h = (k < KHOPS);
        k_hop<<<hop_blocks, 256>>>(flip, k, N, (float4*)out, do_out, write_h);
    }
}